// round 11
// baseline (speedup 1.0000x reference)
#include <cuda_runtime.h>
#include <cstdint>

// MMI softmax loss — collapsed gather form, single launch.
// Structure = R7 (empirical best, 6.624us): 64 single-warp blocks publish f32
// partials via st.global.cg + gpu-scope acq_rel arrival counter; the LAST
// arriving warp alone folds the 64 partials in a fixed shuffle tree
// (bit-deterministic) and writes the scalar. Merged with the main-path cuts
// from R9/R10: __fdividef, 32-bit element offsets precomputed under the tgt
// load's latency, __launch_bounds__(32,1).
//
//   out = -(1/2048) * sum_d  emb[d, t_d] / (sum_{j=1..4} emb[d + j*2048, t_d])

#define DIM   2048
#define NCLS  32000
#define NBLK  64
#define TPB   32    // NBLK * TPB == DIM, one d per thread, one warp per block

__device__ float        g_partial[NBLK];
__device__ unsigned int g_count = 0;   // always left at 0 by the last warp

__global__ void __launch_bounds__(TPB, 1)
mmi_fused_kernel(const float* __restrict__ emb,
                 const int* __restrict__ tgt,
                 float* __restrict__ out) {
    const int lane = threadIdx.x;
    const int d = blockIdx.x * TPB + lane;          // 0..2047, exact cover

    // issue the target load first; 32-bit row offsets (max 10239*32000 =
    // 3.28e8 < 2^31) are computed under its latency
    const int t = __ldg(&tgt[d]);                   // coalesced: 1 line/warp

    const unsigned o0 = (unsigned)d * (unsigned)NCLS;
    const unsigned o1 = o0 + 1u * DIM * NCLS;
    const unsigned o2 = o0 + 2u * DIM * NCLS;
    const unsigned o3 = o0 + 3u * DIM * NCLS;
    const unsigned o4 = o0 + 4u * DIM * NCLS;

    // 5 independent gathers (MLP=5; post-t math = IADD + IMAD.WIDE each)
    const float ex = __ldg(emb + (size_t)(o0 + (unsigned)t));
    const float c0 = __ldg(emb + (size_t)(o1 + (unsigned)t));
    const float c1 = __ldg(emb + (size_t)(o2 + (unsigned)t));
    const float c2 = __ldg(emb + (size_t)(o3 + (unsigned)t));
    const float c3 = __ldg(emb + (size_t)(o4 + (unsigned)t));

    // fast divide: MUFU.RCP + mul (2^-22 rel err, far under the 1e-3 budget)
    float v = __fdividef(ex, ((c0 + c1) + c2) + c3);

    // intra-warp reduce (fixed tree)
    #pragma unroll
    for (int o = 16; o; o >>= 1)
        v += __shfl_xor_sync(0xffffffffu, v, o);

    // Lane 0: publish partial to L2 (st.global.cg — bypasses L1), arrive with
    // a gpu-scope acq_rel atomic (release orders the store; acquire covers
    // the last warp's reads). No fences -> no CCTL.IVALL anywhere.
    unsigned prev = 0;
    if (lane == 0) {
        asm volatile(
            "st.global.cg.f32 [%1], %2;\n\t"
            "atom.acq_rel.gpu.global.add.u32 %0, [%3], 1;\n\t"
            : "=r"(prev)
            : "l"(&g_partial[blockIdx.x]), "f"(v), "l"(&g_count)
            : "memory");
    }
    const bool is_last =
        (__shfl_sync(0xffffffffu, prev, 0) == (unsigned)(NBLK - 1));

    if (is_last) {
        // only ONE block runs this tail: fold 64 partials, fixed order
        float p0, p1;
        asm volatile("ld.acquire.gpu.global.f32 %0, [%1];"
                     : "=f"(p0) : "l"(&g_partial[lane]) : "memory");
        asm volatile("ld.acquire.gpu.global.f32 %0, [%1];"
                     : "=f"(p1) : "l"(&g_partial[lane + 32]) : "memory");
        float p = p0 + p1;
        #pragma unroll
        for (int o = 16; o; o >>= 1)
            p += __shfl_xor_sync(0xffffffffu, p, o);
        if (lane == 0) {
            *out = -(p / (float)DIM);
            g_count = 0;   // re-arm; visible at kernel boundary before replay
        }
    }
}

extern "C" void kernel_launch(void* const* d_in, const int* in_sizes, int n_in,
                              void* d_out, int out_size) {
    const float* emb = (const float*)d_in[0];   // embeddings [10240, 32000] f32
    const int*   tgt = (const int*)d_in[1];     // targets [2048] i32

    mmi_fused_kernel<<<NBLK, TPB>>>(emb, tgt, (float*)d_out);
}